// round 15
// baseline (speedup 1.0000x reference)
#include <cuda_runtime.h>
#include <math.h>
#include <stdint.h>

#define HX_B 16
#define HX_C 256
#define HX_H 128
#define HX_W 128
#define HX_HW (HX_H * HX_W)      // 16384
#define HX_HW4 (HX_HW / 4)       // 4096

#define CH_B 2                   // batches per chunk
#define NCHUNK (HX_B / CH_B)     // 8
#define CHUNK_Q (CH_B * HX_HW4)  // 8192 pixel-quads per chunk

#define GRID 148                 // 1 block per SM (both B300=148 / GB300=152)
#define QPB 56                   // quads per block: 148*56 = 8288 >= 8192
#define TILE_F4 (QPB * HX_C)     // 14336 float4 = 224 KiB
#define SMEM_BYTES (TILE_F4 * 16 + 1024)   // tile + fac pad = 230400 B

// scratch (device globals: allocation-free per harness rules)
__device__ float    g_avg[HX_B * HX_HW];
__device__ float    g_max[HX_B * HX_HW];
__device__ unsigned g_tick;      // monotonic grid-barrier ticket (never reset)

// ---------------------------------------------------------------------------
// Grid barrier: monotonic ticket counter — safe across graph replays without
// reset. All GRID blocks are co-resident (1/SM via smem), so no deadlock.
// ---------------------------------------------------------------------------
__device__ __forceinline__ void grid_bar() {
    __syncthreads();
    if (threadIdx.x == 0) {
        __threadfence();                       // publish my phase's writes
        unsigned t = atomicAdd(&g_tick, 1u);
        unsigned target = (t / GRID + 1u) * GRID;
        unsigned v;
        for (;;) {
            asm volatile("ld.acquire.gpu.u32 %0, [%1];"
                         : "=r"(v) : "l"(&g_tick));
            if (v >= target) break;
            __nanosleep(64);
        }
    }
    __syncthreads();
}

__device__ __forceinline__ void cp_async16(uint32_t smem_addr,
                                           const void* gptr) {
    asm volatile("cp.async.cg.shared.global [%0], [%1], 16;"
                 :: "r"(smem_addr), "l"(gptr));
}

__device__ __forceinline__ float ld_plane(const float* __restrict__ y,
                                          int h, int w) {
    return (h >= 0 && h < HX_H && w >= 0 && w < HX_W) ? __ldg(y + h * HX_W + w)
                                                      : 0.f;
}

// ---------------------------------------------------------------------------
// Persistent fused kernel: per chunk — load tile to SMEM, reduce, grid-bar,
// stencil factors, apply+store from SMEM. x crosses LTS exactly once.
// ---------------------------------------------------------------------------
__global__ void __launch_bounds__(256) fused_kernel(const float4* __restrict__ x4,
                                                    float4* __restrict__ o4,
                                                    const float* __restrict__ wts) {
    extern __shared__ float4 s_tile[];                 // [TILE_F4]
    float* s_fac = reinterpret_cast<float*>(s_tile + TILE_F4);   // [224]

    int tid = threadIdx.x;
    int blk = blockIdx.x;
    float4* av4 = reinterpret_cast<float4*>(g_avg);
    float4* mx4 = reinterpret_cast<float4*>(g_max);

    for (int ch = 0; ch < NCHUNK; ch++) {
        int b0 = ch * CH_B;

        // ---- phase 1a: tile load (cp.async, flat = c*QPB + q) ----
        for (int i = tid; i < TILE_F4; i += 256) {
            int c = i / QPB;
            int q = i - c * QPB;
            int G = blk * QPB + q;
            if (G < CHUNK_Q) {
                int b  = b0 + (G >> 12);
                int qb = G & (HX_HW4 - 1);
                const float4* src = x4 + ((size_t)(b * HX_C + c) * HX_HW4 + qb);
                cp_async16((uint32_t)__cvta_generic_to_shared(s_tile + i), src);
            }
        }
        asm volatile("cp.async.commit_group;" ::: "memory");
        asm volatile("cp.async.wait_group 0;"  ::: "memory");
        __syncthreads();

        // ---- phase 1b: reduce (4 lanes per quad, 64 ch each, shfl combine) ----
        if (tid < 224) {                      // warps 0-6; warp 7 idle
            int q = tid >> 2;
            int s = tid & 3;
            const float4* col = s_tile + q;
            float sx = 0.f, sy = 0.f, sz = 0.f, sw = 0.f;
            float ax = -INFINITY, ay = -INFINITY, az = -INFINITY, aw = -INFINITY;
            int cbase = s * 64;
            #pragma unroll 16
            for (int c = 0; c < 64; c++) {
                float4 v = col[(size_t)(cbase + c) * QPB];
                sx += v.x; sy += v.y; sz += v.z; sw += v.w;
                ax = fmaxf(ax, v.x); ay = fmaxf(ay, v.y);
                az = fmaxf(az, v.z); aw = fmaxf(aw, v.w);
            }
            // combine the 4 slice-lanes (same warp, lanes differ in bits 0-1)
            #pragma unroll
            for (int d = 1; d <= 2; d <<= 1) {
                sx += __shfl_xor_sync(0xffffffffu, sx, d);
                sy += __shfl_xor_sync(0xffffffffu, sy, d);
                sz += __shfl_xor_sync(0xffffffffu, sz, d);
                sw += __shfl_xor_sync(0xffffffffu, sw, d);
                ax = fmaxf(ax, __shfl_xor_sync(0xffffffffu, ax, d));
                ay = fmaxf(ay, __shfl_xor_sync(0xffffffffu, ay, d));
                az = fmaxf(az, __shfl_xor_sync(0xffffffffu, az, d));
                aw = fmaxf(aw, __shfl_xor_sync(0xffffffffu, aw, d));
            }
            int G = blk * QPB + q;
            if (s == 0 && G < CHUNK_Q) {
                int b  = b0 + (G >> 12);
                int qb = G & (HX_HW4 - 1);
                const float inv = 1.0f / HX_C;
                av4[b * HX_HW4 + qb] = make_float4(sx * inv, sy * inv,
                                                   sz * inv, sw * inv);
                mx4[b * HX_HW4 + qb] = make_float4(ax, ay, az, aw);
            }
        }

        grid_bar();                            // avg/max now globally visible

        // ---- phase 2a: stencil + sigmoid factors (one pixel per thread) ----
        if (tid < 224) {
            int q   = tid >> 2;
            int sub = tid & 3;
            int G   = blk * QPB + q;
            if (G < CHUNK_Q) {
                int b  = b0 + (G >> 12);
                int qb = G & (HX_HW4 - 1);
                int h  = qb >> 5;
                int w  = (qb & 31) * 4 + sub;
                float acc = 0.f;
                #pragma unroll
                for (int m = 0; m < 2; m++) {
                    const float* y = (m == 0 ? g_avg : g_max) + b * HX_HW;
                    float p0 = __ldg(wts + b * 8 + m * 4 + 0);
                    float p1 = __ldg(wts + b * 8 + m * 4 + 1);
                    float p2 = __ldg(wts + b * 8 + m * 4 + 2);
                    float p3 = __ldg(wts + b * 8 + m * 4 + 3);
                    float pc = -(p0 + p1 + p2 + p3);
                    acc += p0 * ld_plane(y, h - 1, w)
                         + p1 * ld_plane(y, h + 1, w)
                         + p2 * ld_plane(y, h, w - 1)
                         + p3 * ld_plane(y, h, w + 1)
                         + pc * ld_plane(y, h, w);
                }
                s_fac[tid] = 1.0f + 1.0f / (1.0f + __expf(-acc));
            }
        }
        __syncthreads();

        // ---- phase 2b: apply from SMEM, stream out (evict-first stores) ----
        const float4* fac4 = reinterpret_cast<const float4*>(s_fac);
        for (int i = tid; i < TILE_F4; i += 256) {
            int c = i / QPB;
            int q = i - c * QPB;
            int G = blk * QPB + q;
            if (G < CHUNK_Q) {
                int b  = b0 + (G >> 12);
                int qb = G & (HX_HW4 - 1);
                float4 v = s_tile[i];
                float4 f = fac4[q];
                v.x *= f.x; v.y *= f.y; v.z *= f.z; v.w *= f.w;
                __stcs(o4 + ((size_t)(b * HX_C + c) * HX_HW4 + qb), v);
            }
        }
        __syncthreads();   // WAR: all LDS of this tile done before next cp.async
    }
}

extern "C" void kernel_launch(void* const* d_in, const int* in_sizes, int n_in,
                              void* d_out, int out_size) {
    const float4* x4  = (const float4*)d_in[0];
    const float*  wts = (const float*)d_in[1];
    float4*       o4  = (float4*)d_out;

    static bool init = false;
    if (!init) {
        cudaFuncSetAttribute(fused_kernel,
                             cudaFuncAttributeMaxDynamicSharedMemorySize,
                             SMEM_BYTES);
        init = true;
    }
    fused_kernel<<<GRID, 256, SMEM_BYTES>>>(x4, o4, wts);
}

// round 16
// speedup vs baseline: 1.2157x; 1.2157x over previous
#include <cuda_runtime.h>
#include <cuda.h>
#include <math.h>
#include <stdint.h>

#define HX_B 16
#define HX_C 256
#define HX_H 128
#define HX_W 128
#define HX_HW (HX_H * HX_W)      // 16384
#define HX_HW4 (HX_HW / 4)       // 4096

#define NCHUNK 16                // 1 batch per chunk
#define GRID 148                 // <= SM count on both B300(148)/GB300(152)
#define QPB 28                   // quads per block: 148*28 = 4144 >= 4096
#define HALF_Q 14                // quads per TMA box (224B row)
#define ROW_BYTES (HALF_Q * 16)          // 224
#define REGION_BYTES (ROW_BYTES * HX_C)  // 57344
#define TILE_BYTES (2 * REGION_BYTES)    // 114688 per buffer
#define SMEM_DYN (2 * TILE_BYTES)        // 229376 (two buffers)

// scratch (device globals: allocation-free per harness rules)
__device__ float    g_avg[HX_B * HX_HW];
__device__ float    g_max[HX_B * HX_HW];
__device__ unsigned g_tick;      // monotonic grid-barrier ticket (never reset)

// ---------------------------------------------------------------------------
__device__ __forceinline__ uint32_t smem_u32(const void* p) {
    return (uint32_t)__cvta_generic_to_shared(p);
}

__device__ __forceinline__ void grid_bar() {
    __syncthreads();
    if (threadIdx.x == 0) {
        __threadfence();                       // publish avg/max writes
        unsigned t = atomicAdd(&g_tick, 1u);
        unsigned target = (t / GRID + 1u) * GRID;
        unsigned v;
        for (;;) {
            asm volatile("ld.acquire.gpu.u32 %0, [%1];" : "=r"(v) : "l"(&g_tick));
            if (v >= target) break;
            __nanosleep(64);
        }
    }
    __syncthreads();
}

__device__ __forceinline__ void mbar_init(uint32_t mb, uint32_t cnt) {
    asm volatile("mbarrier.init.shared.b64 [%0], %1;" :: "r"(mb), "r"(cnt) : "memory");
}
__device__ __forceinline__ void mbar_expect_tx(uint32_t mb, uint32_t bytes) {
    asm volatile("mbarrier.arrive.expect_tx.shared.b64 _, [%0], %1;"
                 :: "r"(mb), "r"(bytes) : "memory");
}
__device__ __forceinline__ void mbar_wait(uint32_t mb, uint32_t parity) {
    uint32_t done;
    asm volatile(
        "{\n\t.reg .pred p;\n\t"
        "mbarrier.try_wait.parity.acquire.cta.shared::cta.b64 p, [%1], %2;\n\t"
        "selp.b32 %0, 1, 0, p;\n\t}"
        : "=r"(done) : "r"(mb), "r"(parity) : "memory");
    if (!done) {
        asm volatile(
            "{\n\t.reg .pred P1;\n\t"
            "WAIT_LOOP_%=:\n\t"
            "mbarrier.try_wait.parity.acquire.cta.shared::cta.b64 P1, [%0], %1, 0x989680;\n\t"
            "@P1 bra.uni WAIT_DONE_%=;\n\t"
            "bra.uni WAIT_LOOP_%=;\n\t"
            "WAIT_DONE_%=:\n\t}"
            :: "r"(mb), "r"(parity) : "memory");
    }
}
__device__ __forceinline__ void tma_load3d(uint32_t dst, const CUtensorMap* tm,
                                           int x, int y, int z, uint32_t mb) {
    asm volatile(
        "cp.async.bulk.tensor.3d.shared::cluster.global.tile.mbarrier::complete_tx::bytes "
        "[%0], [%1, {%2, %3, %4}], [%5];"
        :: "r"(dst), "l"(tm), "r"(x), "r"(y), "r"(z), "r"(mb) : "memory");
}

__device__ __forceinline__ float ld_plane(const float* __restrict__ y, int h, int w) {
    return (h >= 0 && h < HX_H && w >= 0 && w < HX_W) ? __ldg(y + h * HX_W + w) : 0.f;
}

// ---------------------------------------------------------------------------
// Persistent fused kernel. Per chunk (= 1 batch): TMA tile into smem (double
// buffered, prefetched one chunk ahead) -> in-smem reduce -> grid barrier ->
// stencil+sigmoid -> apply+STG. x crosses the LTS exactly once.
// ---------------------------------------------------------------------------
__global__ void __launch_bounds__(512)
fused_kernel(const __grid_constant__ CUtensorMap tmap,
             float4* __restrict__ o4,
             const float* __restrict__ wts) {
    extern __shared__ __align__(128) unsigned char smem[];
    __shared__ float4 s_sum[2][32];
    __shared__ float4 s_mx[2][32];
    __shared__ __align__(16) float s_fac[QPB * 4];
    __shared__ __align__(8) uint64_t s_mbar[2];

    const int tid = threadIdx.x;
    const int blk = blockIdx.x;
    const int G0  = blk * QPB;
    int nq = HX_HW4 - G0;
    nq = nq < 0 ? 0 : (nq > QPB ? QPB : nq);
    const int nregions = (nq > HALF_Q) ? 2 : (nq > 0 ? 1 : 0);

    float4* av4 = reinterpret_cast<float4*>(g_avg);
    float4* mx4 = reinterpret_cast<float4*>(g_max);

    if (tid == 0) {
        mbar_init(smem_u32(&s_mbar[0]), 1);
        mbar_init(smem_u32(&s_mbar[1]), 1);
    }
    asm volatile("fence.proxy.async.shared::cta;" ::: "memory");
    __syncthreads();

    int ph0 = 0, ph1 = 0;

    // prologue: prefetch chunk 0 into buffer 0
    if (nregions && tid == 0) {
        uint32_t mb = smem_u32(&s_mbar[0]);
        mbar_expect_tx(mb, nregions * REGION_BYTES);
        uint32_t dst = smem_u32(smem);
        tma_load3d(dst, &tmap, G0 * 4, 0, 0, mb);
        if (nregions == 2)
            tma_load3d(dst + REGION_BYTES, &tmap, G0 * 4 + 56, 0, 0, mb);
    }

    for (int ch = 0; ch < NCHUNK; ch++) {
        const int cur = ch & 1;
        unsigned char* tile = smem + cur * TILE_BYTES;

        // prefetch chunk ch+1 into the other buffer (freed by last iter's sync)
        if (ch + 1 < NCHUNK && nregions && tid == 0) {
            const int nxt = cur ^ 1;
            uint32_t mb = smem_u32(&s_mbar[nxt]);
            mbar_expect_tx(mb, nregions * REGION_BYTES);
            uint32_t dst = smem_u32(smem + nxt * TILE_BYTES);
            tma_load3d(dst, &tmap, G0 * 4, 0, ch + 1, mb);
            if (nregions == 2)
                tma_load3d(dst + REGION_BYTES, &tmap, G0 * 4 + 56, 0, ch + 1, mb);
        }

        // wait for this chunk's tile
        if (nregions) {
            mbar_wait(smem_u32(&s_mbar[cur]), cur == 0 ? ph0 : ph1);
            if (cur == 0) ph0 ^= 1; else ph1 ^= 1;
        }
        __syncthreads();

        // ---- reduce: warps 0,1; lane = quad, warp = channel half ----
        if (tid < 64) {
            const int w = tid >> 5;            // channel slice: 0 or 1
            const int q = tid & 31;
            if (q < nq) {
                const int r  = (q >= HALF_Q);
                const int qq = q - r * HALF_Q;
                const unsigned char* p = tile + r * REGION_BYTES + qq * 16
                                       + (size_t)(w * 128) * ROW_BYTES;
                float sx = 0.f, sy = 0.f, sz = 0.f, sw = 0.f;
                float ax = -INFINITY, ay = -INFINITY, az = -INFINITY, aw = -INFINITY;
                #pragma unroll 8
                for (int c = 0; c < 128; c++) {
                    float4 v = *reinterpret_cast<const float4*>(p + (size_t)c * ROW_BYTES);
                    sx += v.x; sy += v.y; sz += v.z; sw += v.w;
                    ax = fmaxf(ax, v.x); ay = fmaxf(ay, v.y);
                    az = fmaxf(az, v.z); aw = fmaxf(aw, v.w);
                }
                s_sum[w][q] = make_float4(sx, sy, sz, sw);
                s_mx[w][q]  = make_float4(ax, ay, az, aw);
            }
        }
        __syncthreads();

        // combine the two channel halves, write avg/max planes
        if (tid < nq) {
            float4 a0 = s_sum[0][tid], a1 = s_sum[1][tid];
            float4 m0 = s_mx[0][tid],  m1 = s_mx[1][tid];
            const float inv = 1.0f / HX_C;
            float4 a = make_float4((a0.x + a1.x) * inv, (a0.y + a1.y) * inv,
                                   (a0.z + a1.z) * inv, (a0.w + a1.w) * inv);
            float4 m = make_float4(fmaxf(m0.x, m1.x), fmaxf(m0.y, m1.y),
                                   fmaxf(m0.z, m1.z), fmaxf(m0.w, m1.w));
            av4[ch * HX_HW4 + G0 + tid] = a;
            mx4[ch * HX_HW4 + G0 + tid] = m;
        }

        grid_bar();                            // all avg/max globally visible

        // ---- stencil + sigmoid factors: one sub-pixel per thread ----
        if (tid < QPB * 4) {
            const int q   = tid >> 2;
            const int sub = tid & 3;
            if (q < nq) {
                const int qb = G0 + q;
                const int h  = qb >> 5;
                const int w  = (qb & 31) * 4 + sub;
                float acc = 0.f;
                #pragma unroll
                for (int m = 0; m < 2; m++) {
                    const float* y = (m == 0 ? g_avg : g_max) + ch * HX_HW;
                    float p0 = __ldg(wts + ch * 8 + m * 4 + 0);
                    float p1 = __ldg(wts + ch * 8 + m * 4 + 1);
                    float p2 = __ldg(wts + ch * 8 + m * 4 + 2);
                    float p3 = __ldg(wts + ch * 8 + m * 4 + 3);
                    float pc = -(p0 + p1 + p2 + p3);
                    acc += p0 * ld_plane(y, h - 1, w)
                         + p1 * ld_plane(y, h + 1, w)
                         + p2 * ld_plane(y, h, w - 1)
                         + p3 * ld_plane(y, h, w + 1)
                         + pc * ld_plane(y, h, w);
                }
                s_fac[tid] = 1.0f + 1.0f / (1.0f + __expf(-acc));
            }
        }
        __syncthreads();

        // ---- apply + store: 16 warps x 16 rows; lane = quad ----
        {
            const int wid  = tid >> 5;
            const int lane = tid & 31;
            if (lane < nq) {
                const int r  = (lane >= HALF_Q);
                const int qq = lane - r * HALF_Q;
                const float4 f = reinterpret_cast<const float4*>(s_fac)[lane];
                const unsigned char* tbase = tile + r * REGION_BYTES + qq * 16;
                const int qb = G0 + lane;
                #pragma unroll
                for (int j = 0; j < 16; j++) {
                    const int c = wid + (j << 4);
                    float4 v = *reinterpret_cast<const float4*>(
                        tbase + (size_t)c * ROW_BYTES);
                    v.x *= f.x; v.y *= f.y; v.z *= f.z; v.w *= f.w;
                    __stcs(o4 + ((size_t)(ch * HX_C + c) * HX_HW4 + qb), v);
                }
            }
        }
        __syncthreads();   // tile fully consumed before next prefetch overwrites
    }
}

// ---------------------------------------------------------------------------
extern "C" void kernel_launch(void* const* d_in, const int* in_sizes, int n_in,
                              void* d_out, int out_size) {
    const float* wts = (const float*)d_in[1];
    float4*      o4  = (float4*)d_out;

    typedef CUresult (*EncodeFn)(
        CUtensorMap*, CUtensorMapDataType, cuuint32_t, void*,
        const cuuint64_t*, const cuuint64_t*, const cuuint32_t*, const cuuint32_t*,
        CUtensorMapInterleave, CUtensorMapSwizzle, CUtensorMapL2promotion,
        CUtensorMapFloatOOBfill);

    static CUtensorMap tmap;
    static bool init = false;
    if (!init) {
        cudaFuncSetAttribute(fused_kernel,
                             cudaFuncAttributeMaxDynamicSharedMemorySize, SMEM_DYN);
        EncodeFn fn = nullptr;
        cudaDriverEntryPointQueryResult st;
        cudaGetDriverEntryPoint("cuTensorMapEncodeTiled", (void**)&fn,
                                cudaEnableDefault, &st);
        // x viewed as 3D: [16 batches][256 channels][16384 floats (hw)]
        cuuint64_t dims[3]    = {HX_HW, HX_C, HX_B};
        cuuint64_t strides[2] = {(cuuint64_t)HX_HW * 4,
                                 (cuuint64_t)HX_C * HX_HW * 4};
        cuuint32_t box[3]     = {HALF_Q * 4, HX_C, 1};   // 56 floats x 256 rows
        cuuint32_t es[3]      = {1, 1, 1};
        fn(&tmap, CU_TENSOR_MAP_DATA_TYPE_FLOAT32, 3, (void*)d_in[0],
           dims, strides, box, es,
           CU_TENSOR_MAP_INTERLEAVE_NONE, CU_TENSOR_MAP_SWIZZLE_NONE,
           CU_TENSOR_MAP_L2_PROMOTION_L2_128B,
           CU_TENSOR_MAP_FLOAT_OOB_FILL_NONE);
        init = true;
    }
    fused_kernel<<<GRID, 512, SMEM_DYN>>>(tmap, o4, wts);
}